// round 6
// baseline (speedup 1.0000x reference)
#include <cuda_runtime.h>
#include <cuda_bf16.h>

#define NNODES 50000
#define NEDGES 600000

// ---------------- scratch (device globals) -----------------------------------
__device__ int g_is64;
__device__ int g_cnt [NNODES];
__device__ int g_off [NNODES];
__device__ int g_cur [NNODES];
__device__ __align__(8) int g_src32[NEDGES];
__device__ __align__(8) int g_dst32[NEDGES];
__device__ int g_eidx [NEDGES];
__device__ __align__(16) float g_agg1[NNODES * 128];  // mean of x[src] at dst
__device__ __align__(16) float g_h   [NNODES * 128];  // layer1 output (post relu)
__device__ __align__(16) float g_p   [NNODES * 64];   // h @ Wl2
__device__ __align__(16) float g_q   [NNODES * 64];   // h @ Wr2 + bl2

// ---------------- f32x2 helpers -----------------------------------------------
typedef unsigned long long ull;
__device__ __forceinline__ ull pk2(float x, float y) {
    ull r; asm("mov.b64 %0, {%1, %2};" : "=l"(r) : "f"(x), "f"(y)); return r;
}
__device__ __forceinline__ ull pkdup(float x) {
    ull r; asm("mov.b64 %0, {%1, %1};" : "=l"(r) : "f"(x)); return r;
}
__device__ __forceinline__ void ffma2(ull& d, ull a, ull b) {
    asm("fma.rn.f32x2 %0, %1, %2, %0;" : "+l"(d) : "l"(a), "l"(b));
}
__device__ __forceinline__ float2 unpk(ull v) {
    float2 r; asm("mov.b64 {%0, %1}, %2;" : "=f"(r.x), "=f"(r.y) : "l"(v)); return r;
}

// ---------------- init: zero counts + dtype detect ---------------------------
__global__ void init_kernel(const int* __restrict__ ei32) {
    int i = blockIdx.x * blockDim.x + threadIdx.x;
    if (i < NNODES) g_cnt[i] = 0;
    if (i == 0) {
        int allzero = 1;
        #pragma unroll
        for (int j = 0; j < 64; j++)
            if (ei32[2 * j + 1] != 0) allzero = 0;
        g_is64 = allzero;
    }
}

// ---------------- hist: 2 edges per thread -----------------------------------
__global__ void hist_kernel(const void* __restrict__ ei) {
    int t = blockIdx.x * blockDim.x + threadIdx.x;
    int e = t * 2;
    if (e >= NEDGES) return;
    int s0, s1, d0, d1;
    if (g_is64) {
        const long long* e64 = (const long long*)ei;
        longlong2 ss = *(const longlong2*)(e64 + e);
        longlong2 dd = *(const longlong2*)(e64 + NEDGES + e);
        s0 = (int)ss.x; s1 = (int)ss.y; d0 = (int)dd.x; d1 = (int)dd.y;
    } else {
        const int* e32 = (const int*)ei;
        int2 ss = *(const int2*)(e32 + e);
        int2 dd = *(const int2*)(e32 + NEDGES + e);
        s0 = ss.x; s1 = ss.y; d0 = dd.x; d1 = dd.y;
    }
    s0 = min(max(s0, 0), NNODES - 1); s1 = min(max(s1, 0), NNODES - 1);
    d0 = min(max(d0, 0), NNODES - 1); d1 = min(max(d1, 0), NNODES - 1);
    *(int2*)(g_src32 + e) = make_int2(s0, s1);
    *(int2*)(g_dst32 + e) = make_int2(d0, d1);
    atomicAdd(&g_cnt[d0], 1);
    atomicAdd(&g_cnt[d1], 1);
}

// ---------------- single-block exclusive scan of g_cnt -----------------------
#define SCAN_T 1024
#define SCAN_E 49   // 1024*49 = 50176 >= 50000
__global__ void scan_kernel() {
    __shared__ int part[SCAN_T];
    int tid = threadIdx.x;
    int base = tid * SCAN_E;
    int sum = 0;
    #pragma unroll 7
    for (int j = 0; j < SCAN_E; j++) {
        int idx = base + j;
        if (idx < NNODES) sum += g_cnt[idx];
    }
    part[tid] = sum;
    __syncthreads();
    #pragma unroll
    for (int d = 1; d < SCAN_T; d <<= 1) {
        int t = (tid >= d) ? part[tid - d] : 0;
        __syncthreads();
        part[tid] += t;
        __syncthreads();
    }
    int run = (tid > 0) ? part[tid - 1] : 0;
    #pragma unroll 7
    for (int j = 0; j < SCAN_E; j++) {
        int idx = base + j;
        if (idx < NNODES) {
            int v = g_cnt[idx];        // L1 hit (cached from pass 1)
            g_off[idx] = run;
            g_cur[idx] = run;
            run += v;
        }
    }
}

// ---------------- bucket fill -------------------------------------------------
__global__ void fill_kernel() {
    int e = blockIdx.x * blockDim.x + threadIdx.x;
    if (e >= NEDGES) return;
    int d = g_dst32[e];
    int pos = atomicAdd(&g_cur[d], 1);
    if (pos >= 0 && pos < NEDGES) g_eidx[pos] = g_src32[e];
}

// ---------------- gather layer 1: warp per node, mean of x[src] -------------
__global__ void gather1_kernel(const float4* __restrict__ x4) {
    int w    = (blockIdx.x * blockDim.x + threadIdx.x) >> 5;
    int lane = threadIdx.x & 31;
    if (w >= NNODES) return;
    int beg = g_off[w];
    int c   = g_cnt[w];
    float4 acc = make_float4(0.f, 0.f, 0.f, 0.f);
    int i = 0;
    for (; i + 3 < c; i += 4) {
        int s0 = g_eidx[beg + i];
        int s1 = g_eidx[beg + i + 1];
        int s2 = g_eidx[beg + i + 2];
        int s3 = g_eidx[beg + i + 3];
        float4 v0 = x4[s0 * 32 + lane];
        float4 v1 = x4[s1 * 32 + lane];
        float4 v2 = x4[s2 * 32 + lane];
        float4 v3 = x4[s3 * 32 + lane];
        acc.x += (v0.x + v1.x) + (v2.x + v3.x);
        acc.y += (v0.y + v1.y) + (v2.y + v3.y);
        acc.z += (v0.z + v1.z) + (v2.z + v3.z);
        acc.w += (v0.w + v1.w) + (v2.w + v3.w);
    }
    for (; i < c; i++) {
        int s0 = g_eidx[beg + i];
        float4 v0 = x4[s0 * 32 + lane];
        acc.x += v0.x; acc.y += v0.y; acc.z += v0.z; acc.w += v0.w;
    }
    float rd = 1.0f / (float)max(c, 1);
    acc.x *= rd; acc.y *= rd; acc.z *= rd; acc.w *= rd;
    ((float4*)g_agg1)[w * 32 + lane] = acc;
}

// ---------------- GEMM1: h = relu([agg1 ; x] @ [Wl1;Wr1] + bl1) --------------
// BM=64, BN=128, K=256. 256 threads; thread tile 8 rows (4 M-pairs) x 4 cols.
// As stored K-MAJOR ([256][64]) so M-pairs are free register pairs; only B is
// duplicated (4 pkdup/k). SMEM: Ws 128KB + As 64KB = 192KB.
__global__ void __launch_bounds__(256, 1)
gemm1_kernel(const float4* __restrict__ x4,
             const float4* __restrict__ Wl1,   // [128][32] f4
             const float4* __restrict__ Wr1,   // [128][32] f4
             const float4* __restrict__ bl1) { // [32] f4
    extern __shared__ float sm[];
    float* Ws = sm;                 // [256][128]
    float* As = sm + 256 * 128;     // [256][64]  k-major
    int tid = threadIdx.x;
    int tx = tid & 31, ty = tid >> 5;
    int m0 = blockIdx.x * 64;

    float4* Ws4 = (float4*)Ws;
    #pragma unroll
    for (int i = tid; i < 8192; i += 256) {
        int k = i >> 5, c = i & 31;
        Ws4[i] = (k < 128) ? Wl1[k * 32 + c] : Wr1[(k - 128) * 32 + c];
    }
    // A panel, transposed store: r=i&63 keeps lanes on consecutive smem floats
    const float4* agg4 = (const float4*)g_agg1;
    #pragma unroll
    for (int i = tid; i < 4096; i += 256) {
        int r = i & 63, c = i >> 6;
        int m = m0 + r;
        float4 v = make_float4(0.f, 0.f, 0.f, 0.f);
        if (m < NNODES)
            v = (c < 32) ? agg4[m * 32 + c] : x4[m * 32 + (c - 32)];
        As[(4 * c + 0) * 64 + r] = v.x;
        As[(4 * c + 1) * 64 + r] = v.y;
        As[(4 * c + 2) * 64 + r] = v.z;
        As[(4 * c + 3) * 64 + r] = v.w;
    }
    __syncthreads();

    ull acc[4][4] = {};   // [m-pair][n]
    #pragma unroll 4
    for (int k = 0; k < 256; k++) {
        const float* arow = As + k * 64 + ty * 8;
        float4 a0 = *(const float4*)arow;
        float4 a1 = *(const float4*)(arow + 4);
        ull ap[4];
        ap[0] = pk2(a0.x, a0.y); ap[1] = pk2(a0.z, a0.w);
        ap[2] = pk2(a1.x, a1.y); ap[3] = pk2(a1.z, a1.w);
        float4 b = Ws4[k * 32 + tx];
        ull bd0 = pkdup(b.x), bd1 = pkdup(b.y), bd2 = pkdup(b.z), bd3 = pkdup(b.w);
        #pragma unroll
        for (int ip = 0; ip < 4; ip++) {
            ffma2(acc[ip][0], ap[ip], bd0);
            ffma2(acc[ip][1], ap[ip], bd1);
            ffma2(acc[ip][2], ap[ip], bd2);
            ffma2(acc[ip][3], ap[ip], bd3);
        }
    }

    float4 bias = bl1[tx];
    float4* h4 = (float4*)g_h;
    #pragma unroll
    for (int ip = 0; ip < 4; ip++) {
        float2 c0 = unpk(acc[ip][0]), c1 = unpk(acc[ip][1]);
        float2 c2 = unpk(acc[ip][2]), c3 = unpk(acc[ip][3]);
        int m = m0 + ty * 8 + 2 * ip;
        if (m < NNODES) {
            float4 o;
            o.x = fmaxf(c0.x + bias.x, 0.f);
            o.y = fmaxf(c1.x + bias.y, 0.f);
            o.z = fmaxf(c2.x + bias.z, 0.f);
            o.w = fmaxf(c3.x + bias.w, 0.f);
            h4[m * 32 + tx] = o;
        }
        if (m + 1 < NNODES) {
            float4 o;
            o.x = fmaxf(c0.y + bias.x, 0.f);
            o.y = fmaxf(c1.y + bias.y, 0.f);
            o.z = fmaxf(c2.y + bias.z, 0.f);
            o.w = fmaxf(c3.y + bias.w, 0.f);
            h4[(m + 1) * 32 + tx] = o;
        }
    }
}

// ---------------- GEMM2: p = h@Wl2 ; q = h@Wr2 + bl2 -------------------------
// BM=64, BN=128 (cols 0..63 -> p, 64..127 -> q), K=128. Same scheme as gemm1.
// SMEM: Ws 64KB + As 32KB = 96KB -> 2 blocks/SM.
__global__ void __launch_bounds__(256, 2)
gemm2_kernel(const float4* __restrict__ Wl2,   // [128][16] f4
             const float4* __restrict__ Wr2,   // [128][16] f4
             const float4* __restrict__ bl2) { // [16] f4
    extern __shared__ float sm[];
    float* Ws = sm;                 // [128][128]
    float* As = sm + 128 * 128;     // [128][64]  k-major
    int tid = threadIdx.x;
    int tx = tid & 31, ty = tid >> 5;
    int m0 = blockIdx.x * 64;

    float4* Ws4 = (float4*)Ws;
    #pragma unroll
    for (int i = tid; i < 4096; i += 256) {
        int k = i >> 5, c = i & 31;
        Ws4[i] = (c < 16) ? Wl2[k * 16 + c] : Wr2[k * 16 + (c - 16)];
    }
    const float4* h4 = (const float4*)g_h;
    #pragma unroll
    for (int i = tid; i < 2048; i += 256) {
        int r = i & 63, c = i >> 6;   // c in 0..31
        int m = m0 + r;
        float4 v = (m < NNODES) ? h4[m * 32 + c] : make_float4(0.f, 0.f, 0.f, 0.f);
        As[(4 * c + 0) * 64 + r] = v.x;
        As[(4 * c + 1) * 64 + r] = v.y;
        As[(4 * c + 2) * 64 + r] = v.z;
        As[(4 * c + 3) * 64 + r] = v.w;
    }
    __syncthreads();

    ull acc[4][4] = {};
    #pragma unroll 4
    for (int k = 0; k < 128; k++) {
        const float* arow = As + k * 64 + ty * 8;
        float4 a0 = *(const float4*)arow;
        float4 a1 = *(const float4*)(arow + 4);
        ull ap[4];
        ap[0] = pk2(a0.x, a0.y); ap[1] = pk2(a0.z, a0.w);
        ap[2] = pk2(a1.x, a1.y); ap[3] = pk2(a1.z, a1.w);
        float4 b = Ws4[k * 32 + tx];
        ull bd0 = pkdup(b.x), bd1 = pkdup(b.y), bd2 = pkdup(b.z), bd3 = pkdup(b.w);
        #pragma unroll
        for (int ip = 0; ip < 4; ip++) {
            ffma2(acc[ip][0], ap[ip], bd0);
            ffma2(acc[ip][1], ap[ip], bd1);
            ffma2(acc[ip][2], ap[ip], bd2);
            ffma2(acc[ip][3], ap[ip], bd3);
        }
    }

    float4* p4 = (float4*)g_p;
    float4* q4 = (float4*)g_q;
    if (tx < 16) {
        #pragma unroll
        for (int ip = 0; ip < 4; ip++) {
            float2 c0 = unpk(acc[ip][0]), c1 = unpk(acc[ip][1]);
            float2 c2 = unpk(acc[ip][2]), c3 = unpk(acc[ip][3]);
            int m = m0 + ty * 8 + 2 * ip;
            if (m < NNODES)
                p4[m * 16 + tx] = make_float4(c0.x, c1.x, c2.x, c3.x);
            if (m + 1 < NNODES)
                p4[(m + 1) * 16 + tx] = make_float4(c0.y, c1.y, c2.y, c3.y);
        }
    } else {
        float4 bias = bl2[tx - 16];
        #pragma unroll
        for (int ip = 0; ip < 4; ip++) {
            float2 c0 = unpk(acc[ip][0]), c1 = unpk(acc[ip][1]);
            float2 c2 = unpk(acc[ip][2]), c3 = unpk(acc[ip][3]);
            int m = m0 + ty * 8 + 2 * ip;
            if (m < NNODES)
                q4[m * 16 + (tx - 16)] = make_float4(c0.x + bias.x, c1.x + bias.y,
                                                     c2.x + bias.z, c3.x + bias.w);
            if (m + 1 < NNODES)
                q4[(m + 1) * 16 + (tx - 16)] = make_float4(c0.y + bias.x, c1.y + bias.y,
                                                           c2.y + bias.z, c3.y + bias.w);
        }
    }
}

// ---------------- gather layer 2 + log_softmax (fused) -----------------------
__global__ void gather2_final_kernel(float* __restrict__ out) {
    int w    = (blockIdx.x * blockDim.x + threadIdx.x) >> 5;
    int lane = threadIdx.x & 31;
    if (w >= NNODES) return;
    int beg = g_off[w];
    int c   = g_cnt[w];
    const float2* p2 = (const float2*)g_p;
    float2 acc = make_float2(0.f, 0.f);
    int i = 0;
    for (; i + 3 < c; i += 4) {
        int s0 = g_eidx[beg + i];
        int s1 = g_eidx[beg + i + 1];
        int s2 = g_eidx[beg + i + 2];
        int s3 = g_eidx[beg + i + 3];
        float2 v0 = p2[s0 * 32 + lane];
        float2 v1 = p2[s1 * 32 + lane];
        float2 v2 = p2[s2 * 32 + lane];
        float2 v3 = p2[s3 * 32 + lane];
        acc.x += (v0.x + v1.x) + (v2.x + v3.x);
        acc.y += (v0.y + v1.y) + (v2.y + v3.y);
    }
    for (; i < c; i++) {
        int s0 = g_eidx[beg + i];
        float2 v0 = p2[s0 * 32 + lane];
        acc.x += v0.x; acc.y += v0.y;
    }
    float rd = 1.0f / (float)max(c, 1);
    float2 q = ((const float2*)g_q)[w * 32 + lane];
    float v0 = acc.x * rd + q.x;
    float v1 = acc.y * rd + q.y;

    float mx = fmaxf(v0, v1);
    #pragma unroll
    for (int o = 16; o; o >>= 1) mx = fmaxf(mx, __shfl_xor_sync(0xffffffffu, mx, o));
    float s = expf(v0 - mx) + expf(v1 - mx);
    #pragma unroll
    for (int o = 16; o; o >>= 1) s += __shfl_xor_sync(0xffffffffu, s, o);
    float ls = logf(s) + mx;

    ((float2*)out)[w * 32 + lane] = make_float2(v0 - ls, v1 - ls);
}

// ---------------- launch ------------------------------------------------------
extern "C" void kernel_launch(void* const* d_in, const int* in_sizes, int n_in,
                              void* d_out, int out_size) {
    const float4* x4   = (const float4*)d_in[0];
    const void*   ei   = d_in[1];
    const float4* Wl1  = (const float4*)d_in[2];
    const float4* bl1  = (const float4*)d_in[3];
    const float4* Wr1  = (const float4*)d_in[4];
    const float4* Wl2  = (const float4*)d_in[5];
    const float4* bl2  = (const float4*)d_in[6];
    const float4* Wr2  = (const float4*)d_in[7];
    float*        out  = (float*)d_out;

    cudaFuncSetAttribute(gemm1_kernel, cudaFuncAttributeMaxDynamicSharedMemorySize, 196608);
    cudaFuncSetAttribute(gemm2_kernel, cudaFuncAttributeMaxDynamicSharedMemorySize, 98304);

    init_kernel<<<(NNODES + 255) / 256, 256>>>((const int*)ei);
    hist_kernel<<<(NEDGES / 2 + 255) / 256, 256>>>(ei);
    scan_kernel<<<1, SCAN_T>>>();
    fill_kernel<<<(NEDGES + 255) / 256, 256>>>();

    gather1_kernel<<<(NNODES * 32 + 255) / 256, 256>>>(x4);
    gemm1_kernel<<<(NNODES + 63) / 64, 256, 196608>>>(x4, Wl1, Wr1, bl1);
    gemm2_kernel<<<(NNODES + 63) / 64, 256, 98304>>>(Wl2, Wr2, bl2);
    gather2_final_kernel<<<(NNODES * 32 + 255) / 256, 256>>>(out);
}

// round 7
// speedup vs baseline: 1.3282x; 1.3282x over previous
#include <cuda_runtime.h>
#include <cuda_bf16.h>

#define NNODES 50000
#define NEDGES 600000
#define CHUNK  1024
#define NCHUNK 49   // ceil(50000/1024)

// ---------------- scratch (device globals) -----------------------------------
__device__ int g_is64;
__device__ int g_cnt [NNODES];
__device__ int g_off [NNODES];
__device__ int g_cur [NNODES];
__device__ __align__(8) int g_src32[NEDGES];
__device__ __align__(8) int g_dst32[NEDGES];
__device__ int g_eidx [NEDGES];
__device__ int g_chunksum[64];
__device__ int g_chunkoff[64];
__device__ __align__(16) float g_agg1[NNODES * 128];  // mean of x[src] at dst
__device__ __align__(16) float g_h   [NNODES * 128];  // layer1 output (post relu)
__device__ __align__(16) float g_p   [NNODES * 64];   // h @ Wl2
__device__ __align__(16) float g_q   [NNODES * 64];   // h @ Wr2 + bl2

// ---------------- f32x2 helpers -----------------------------------------------
typedef unsigned long long ull;
__device__ __forceinline__ ull pk2(float x, float y) {
    ull r; asm("mov.b64 %0, {%1, %2};" : "=l"(r) : "f"(x), "f"(y)); return r;
}
__device__ __forceinline__ ull pkdup(float x) {
    ull r; asm("mov.b64 %0, {%1, %1};" : "=l"(r) : "f"(x)); return r;
}
__device__ __forceinline__ void ffma2(ull& d, ull a, ull b) {
    asm("fma.rn.f32x2 %0, %1, %2, %0;" : "+l"(d) : "l"(a), "l"(b));
}
__device__ __forceinline__ float2 unpk(ull v) {
    float2 r; asm("mov.b64 {%0, %1}, %2;" : "=f"(r.x), "=f"(r.y) : "l"(v)); return r;
}

// ---------------- init: zero counts + dtype detect ---------------------------
__global__ void init_kernel(const int* __restrict__ ei32) {
    int i = blockIdx.x * blockDim.x + threadIdx.x;
    if (i < NNODES) g_cnt[i] = 0;
    if (i == 0) {
        int allzero = 1;
        #pragma unroll
        for (int j = 0; j < 64; j++)
            if (ei32[2 * j + 1] != 0) allzero = 0;
        g_is64 = allzero;
    }
}

// ---------------- hist: 2 edges per thread -----------------------------------
__global__ void hist_kernel(const void* __restrict__ ei) {
    int t = blockIdx.x * blockDim.x + threadIdx.x;
    int e = t * 2;
    if (e >= NEDGES) return;
    int s0, s1, d0, d1;
    if (g_is64) {
        const long long* e64 = (const long long*)ei;
        longlong2 ss = *(const longlong2*)(e64 + e);
        longlong2 dd = *(const longlong2*)(e64 + NEDGES + e);
        s0 = (int)ss.x; s1 = (int)ss.y; d0 = (int)dd.x; d1 = (int)dd.y;
    } else {
        const int* e32 = (const int*)ei;
        int2 ss = *(const int2*)(e32 + e);
        int2 dd = *(const int2*)(e32 + NEDGES + e);
        s0 = ss.x; s1 = ss.y; d0 = dd.x; d1 = dd.y;
    }
    s0 = min(max(s0, 0), NNODES - 1); s1 = min(max(s1, 0), NNODES - 1);
    d0 = min(max(d0, 0), NNODES - 1); d1 = min(max(d1, 0), NNODES - 1);
    *(int2*)(g_src32 + e) = make_int2(s0, s1);
    *(int2*)(g_dst32 + e) = make_int2(d0, d1);
    atomicAdd(&g_cnt[d0], 1);
    atomicAdd(&g_cnt[d1], 1);
}

// ---------------- 3-phase multi-block exclusive scan -------------------------
__global__ void scan_p1_kernel() {   // per-chunk sums
    __shared__ int sm[CHUNK];
    int tid = threadIdx.x;
    int idx = blockIdx.x * CHUNK + tid;
    sm[tid] = (idx < NNODES) ? g_cnt[idx] : 0;
    __syncthreads();
    #pragma unroll
    for (int s = CHUNK / 2; s > 0; s >>= 1) {
        if (tid < s) sm[tid] += sm[tid + s];
        __syncthreads();
    }
    if (tid == 0) g_chunksum[blockIdx.x] = sm[0];
}

__global__ void scan_p2_kernel() {   // exclusive scan of chunk sums
    __shared__ int sm[64];
    int tid = threadIdx.x;
    sm[tid] = (tid < NCHUNK) ? g_chunksum[tid] : 0;
    __syncthreads();
    if (tid == 0) {
        int run = 0;
        for (int i = 0; i < NCHUNK; i++) { int v = sm[i]; sm[i] = run; run += v; }
    }
    __syncthreads();
    if (tid < NCHUNK) g_chunkoff[tid] = sm[tid];
}

__global__ void scan_p3_kernel() {   // per-chunk exclusive scan + offset
    __shared__ int sm[CHUNK];
    int tid = threadIdx.x;
    int idx = blockIdx.x * CHUNK + tid;
    int v = (idx < NNODES) ? g_cnt[idx] : 0;
    sm[tid] = v;
    __syncthreads();
    #pragma unroll
    for (int d = 1; d < CHUNK; d <<= 1) {
        int t = (tid >= d) ? sm[tid - d] : 0;
        __syncthreads();
        sm[tid] += t;
        __syncthreads();
    }
    if (idx < NNODES) {
        int off = g_chunkoff[blockIdx.x] + sm[tid] - v;   // exclusive
        g_off[idx] = off;
        g_cur[idx] = off;
    }
}

// ---------------- bucket fill -------------------------------------------------
__global__ void fill_kernel() {
    int e = blockIdx.x * blockDim.x + threadIdx.x;
    if (e >= NEDGES) return;
    int d = g_dst32[e];
    int pos = atomicAdd(&g_cur[d], 1);
    if (pos >= 0 && pos < NEDGES) g_eidx[pos] = g_src32[e];
}

// ---------------- gather layer 1: warp per node, mean of x[src] -------------
__global__ void gather1_kernel(const float4* __restrict__ x4) {
    int w    = (blockIdx.x * blockDim.x + threadIdx.x) >> 5;
    int lane = threadIdx.x & 31;
    if (w >= NNODES) return;
    int beg = g_off[w];
    int c   = g_cnt[w];
    float4 acc = make_float4(0.f, 0.f, 0.f, 0.f);
    int i = 0;
    for (; i + 3 < c; i += 4) {
        int s0 = g_eidx[beg + i];
        int s1 = g_eidx[beg + i + 1];
        int s2 = g_eidx[beg + i + 2];
        int s3 = g_eidx[beg + i + 3];
        float4 v0 = x4[s0 * 32 + lane];
        float4 v1 = x4[s1 * 32 + lane];
        float4 v2 = x4[s2 * 32 + lane];
        float4 v3 = x4[s3 * 32 + lane];
        acc.x += (v0.x + v1.x) + (v2.x + v3.x);
        acc.y += (v0.y + v1.y) + (v2.y + v3.y);
        acc.z += (v0.z + v1.z) + (v2.z + v3.z);
        acc.w += (v0.w + v1.w) + (v2.w + v3.w);
    }
    for (; i < c; i++) {
        int s0 = g_eidx[beg + i];
        float4 v0 = x4[s0 * 32 + lane];
        acc.x += v0.x; acc.y += v0.y; acc.z += v0.z; acc.w += v0.w;
    }
    float rd = 1.0f / (float)max(c, 1);
    acc.x *= rd; acc.y *= rd; acc.z *= rd; acc.w *= rd;
    ((float4*)g_agg1)[w * 32 + lane] = acc;
}

// ---------------- GEMM1: h = relu([agg1 ; x] @ [Wl1;Wr1] + bl1) --------------
// BM=64, BN=128, K=256. 256 threads; thread tile 8 rows (4 M-pairs) x 4 cols.
// As stored K-MAJOR ([256][64]) so M-pairs are free register pairs; only B is
// duplicated (4 pkdup/k). SMEM: Ws 128KB + As 64KB = 192KB.
__global__ void __launch_bounds__(256, 1)
gemm1_kernel(const float4* __restrict__ x4,
             const float4* __restrict__ Wl1,   // [128][32] f4
             const float4* __restrict__ Wr1,   // [128][32] f4
             const float4* __restrict__ bl1) { // [32] f4
    extern __shared__ float sm[];
    float* Ws = sm;                 // [256][128]
    float* As = sm + 256 * 128;     // [256][64]  k-major
    int tid = threadIdx.x;
    int tx = tid & 31, ty = tid >> 5;
    int m0 = blockIdx.x * 64;

    float4* Ws4 = (float4*)Ws;
    #pragma unroll
    for (int i = tid; i < 8192; i += 256) {
        int k = i >> 5, c = i & 31;
        Ws4[i] = (k < 128) ? Wl1[k * 32 + c] : Wr1[(k - 128) * 32 + c];
    }
    const float4* agg4 = (const float4*)g_agg1;
    #pragma unroll
    for (int i = tid; i < 4096; i += 256) {
        int r = i & 63, c = i >> 6;
        int m = m0 + r;
        float4 v = make_float4(0.f, 0.f, 0.f, 0.f);
        if (m < NNODES)
            v = (c < 32) ? agg4[m * 32 + c] : x4[m * 32 + (c - 32)];
        As[(4 * c + 0) * 64 + r] = v.x;
        As[(4 * c + 1) * 64 + r] = v.y;
        As[(4 * c + 2) * 64 + r] = v.z;
        As[(4 * c + 3) * 64 + r] = v.w;
    }
    __syncthreads();

    ull acc[4][4] = {};   // [m-pair][n]
    #pragma unroll 4
    for (int k = 0; k < 256; k++) {
        const float* arow = As + k * 64 + ty * 8;
        float4 a0 = *(const float4*)arow;
        float4 a1 = *(const float4*)(arow + 4);
        ull ap[4];
        ap[0] = pk2(a0.x, a0.y); ap[1] = pk2(a0.z, a0.w);
        ap[2] = pk2(a1.x, a1.y); ap[3] = pk2(a1.z, a1.w);
        float4 b = Ws4[k * 32 + tx];
        ull bd0 = pkdup(b.x), bd1 = pkdup(b.y), bd2 = pkdup(b.z), bd3 = pkdup(b.w);
        #pragma unroll
        for (int ip = 0; ip < 4; ip++) {
            ffma2(acc[ip][0], ap[ip], bd0);
            ffma2(acc[ip][1], ap[ip], bd1);
            ffma2(acc[ip][2], ap[ip], bd2);
            ffma2(acc[ip][3], ap[ip], bd3);
        }
    }

    float4 bias = bl1[tx];
    float4* h4 = (float4*)g_h;
    #pragma unroll
    for (int ip = 0; ip < 4; ip++) {
        float2 c0 = unpk(acc[ip][0]), c1 = unpk(acc[ip][1]);
        float2 c2 = unpk(acc[ip][2]), c3 = unpk(acc[ip][3]);
        int m = m0 + ty * 8 + 2 * ip;
        if (m < NNODES) {
            float4 o;
            o.x = fmaxf(c0.x + bias.x, 0.f);
            o.y = fmaxf(c1.x + bias.y, 0.f);
            o.z = fmaxf(c2.x + bias.z, 0.f);
            o.w = fmaxf(c3.x + bias.w, 0.f);
            h4[m * 32 + tx] = o;
        }
        if (m + 1 < NNODES) {
            float4 o;
            o.x = fmaxf(c0.y + bias.x, 0.f);
            o.y = fmaxf(c1.y + bias.y, 0.f);
            o.z = fmaxf(c2.y + bias.z, 0.f);
            o.w = fmaxf(c3.y + bias.w, 0.f);
            h4[(m + 1) * 32 + tx] = o;
        }
    }
}

// ---------------- GEMM2: p = h@Wl2 ; q = h@Wr2 + bl2 -------------------------
// BM=64, BN=128 (cols 0..63 -> p, 64..127 -> q), K=128. Same scheme as gemm1.
// SMEM: Ws 64KB + As 32KB = 96KB -> 2 blocks/SM.
__global__ void __launch_bounds__(256, 2)
gemm2_kernel(const float4* __restrict__ Wl2,   // [128][16] f4
             const float4* __restrict__ Wr2,   // [128][16] f4
             const float4* __restrict__ bl2) { // [16] f4
    extern __shared__ float sm[];
    float* Ws = sm;                 // [128][128]
    float* As = sm + 128 * 128;     // [128][64]  k-major
    int tid = threadIdx.x;
    int tx = tid & 31, ty = tid >> 5;
    int m0 = blockIdx.x * 64;

    float4* Ws4 = (float4*)Ws;
    #pragma unroll
    for (int i = tid; i < 4096; i += 256) {
        int k = i >> 5, c = i & 31;
        Ws4[i] = (c < 16) ? Wl2[k * 16 + c] : Wr2[k * 16 + (c - 16)];
    }
    const float4* h4 = (const float4*)g_h;
    #pragma unroll
    for (int i = tid; i < 2048; i += 256) {
        int r = i & 63, c = i >> 6;   // c in 0..31
        int m = m0 + r;
        float4 v = (m < NNODES) ? h4[m * 32 + c] : make_float4(0.f, 0.f, 0.f, 0.f);
        As[(4 * c + 0) * 64 + r] = v.x;
        As[(4 * c + 1) * 64 + r] = v.y;
        As[(4 * c + 2) * 64 + r] = v.z;
        As[(4 * c + 3) * 64 + r] = v.w;
    }
    __syncthreads();

    ull acc[4][4] = {};
    #pragma unroll 4
    for (int k = 0; k < 128; k++) {
        const float* arow = As + k * 64 + ty * 8;
        float4 a0 = *(const float4*)arow;
        float4 a1 = *(const float4*)(arow + 4);
        ull ap[4];
        ap[0] = pk2(a0.x, a0.y); ap[1] = pk2(a0.z, a0.w);
        ap[2] = pk2(a1.x, a1.y); ap[3] = pk2(a1.z, a1.w);
        float4 b = Ws4[k * 32 + tx];
        ull bd0 = pkdup(b.x), bd1 = pkdup(b.y), bd2 = pkdup(b.z), bd3 = pkdup(b.w);
        #pragma unroll
        for (int ip = 0; ip < 4; ip++) {
            ffma2(acc[ip][0], ap[ip], bd0);
            ffma2(acc[ip][1], ap[ip], bd1);
            ffma2(acc[ip][2], ap[ip], bd2);
            ffma2(acc[ip][3], ap[ip], bd3);
        }
    }

    float4* p4 = (float4*)g_p;
    float4* q4 = (float4*)g_q;
    if (tx < 16) {
        #pragma unroll
        for (int ip = 0; ip < 4; ip++) {
            float2 c0 = unpk(acc[ip][0]), c1 = unpk(acc[ip][1]);
            float2 c2 = unpk(acc[ip][2]), c3 = unpk(acc[ip][3]);
            int m = m0 + ty * 8 + 2 * ip;
            if (m < NNODES)
                p4[m * 16 + tx] = make_float4(c0.x, c1.x, c2.x, c3.x);
            if (m + 1 < NNODES)
                p4[(m + 1) * 16 + tx] = make_float4(c0.y, c1.y, c2.y, c3.y);
        }
    } else {
        float4 bias = bl2[tx - 16];
        #pragma unroll
        for (int ip = 0; ip < 4; ip++) {
            float2 c0 = unpk(acc[ip][0]), c1 = unpk(acc[ip][1]);
            float2 c2 = unpk(acc[ip][2]), c3 = unpk(acc[ip][3]);
            int m = m0 + ty * 8 + 2 * ip;
            if (m < NNODES)
                q4[m * 16 + (tx - 16)] = make_float4(c0.x + bias.x, c1.x + bias.y,
                                                     c2.x + bias.z, c3.x + bias.w);
            if (m + 1 < NNODES)
                q4[(m + 1) * 16 + (tx - 16)] = make_float4(c0.y + bias.x, c1.y + bias.y,
                                                           c2.y + bias.z, c3.y + bias.w);
        }
    }
}

// ---------------- gather layer 2 + log_softmax (fused) -----------------------
__global__ void gather2_final_kernel(float* __restrict__ out) {
    int w    = (blockIdx.x * blockDim.x + threadIdx.x) >> 5;
    int lane = threadIdx.x & 31;
    if (w >= NNODES) return;
    int beg = g_off[w];
    int c   = g_cnt[w];
    const float2* p2 = (const float2*)g_p;
    float2 acc = make_float2(0.f, 0.f);
    int i = 0;
    for (; i + 3 < c; i += 4) {
        int s0 = g_eidx[beg + i];
        int s1 = g_eidx[beg + i + 1];
        int s2 = g_eidx[beg + i + 2];
        int s3 = g_eidx[beg + i + 3];
        float2 v0 = p2[s0 * 32 + lane];
        float2 v1 = p2[s1 * 32 + lane];
        float2 v2 = p2[s2 * 32 + lane];
        float2 v3 = p2[s3 * 32 + lane];
        acc.x += (v0.x + v1.x) + (v2.x + v3.x);
        acc.y += (v0.y + v1.y) + (v2.y + v3.y);
    }
    for (; i < c; i++) {
        int s0 = g_eidx[beg + i];
        float2 v0 = p2[s0 * 32 + lane];
        acc.x += v0.x; acc.y += v0.y;
    }
    float rd = 1.0f / (float)max(c, 1);
    float2 q = ((const float2*)g_q)[w * 32 + lane];
    float v0 = acc.x * rd + q.x;
    float v1 = acc.y * rd + q.y;

    float mx = fmaxf(v0, v1);
    #pragma unroll
    for (int o = 16; o; o >>= 1) mx = fmaxf(mx, __shfl_xor_sync(0xffffffffu, mx, o));
    float s = expf(v0 - mx) + expf(v1 - mx);
    #pragma unroll
    for (int o = 16; o; o >>= 1) s += __shfl_xor_sync(0xffffffffu, s, o);
    float ls = logf(s) + mx;

    ((float2*)out)[w * 32 + lane] = make_float2(v0 - ls, v1 - ls);
}

// ---------------- launch ------------------------------------------------------
extern "C" void kernel_launch(void* const* d_in, const int* in_sizes, int n_in,
                              void* d_out, int out_size) {
    const float4* x4   = (const float4*)d_in[0];
    const void*   ei   = d_in[1];
    const float4* Wl1  = (const float4*)d_in[2];
    const float4* bl1  = (const float4*)d_in[3];
    const float4* Wr1  = (const float4*)d_in[4];
    const float4* Wl2  = (const float4*)d_in[5];
    const float4* bl2  = (const float4*)d_in[6];
    const float4* Wr2  = (const float4*)d_in[7];
    float*        out  = (float*)d_out;

    cudaFuncSetAttribute(gemm1_kernel, cudaFuncAttributeMaxDynamicSharedMemorySize, 196608);
    cudaFuncSetAttribute(gemm2_kernel, cudaFuncAttributeMaxDynamicSharedMemorySize, 98304);

    init_kernel<<<(NNODES + 255) / 256, 256>>>((const int*)ei);
    hist_kernel<<<(NEDGES / 2 + 255) / 256, 256>>>(ei);
    scan_p1_kernel<<<NCHUNK, CHUNK>>>();
    scan_p2_kernel<<<1, 64>>>();
    scan_p3_kernel<<<NCHUNK, CHUNK>>>();
    fill_kernel<<<(NEDGES + 255) / 256, 256>>>();

    gather1_kernel<<<(NNODES * 32 + 255) / 256, 256>>>(x4);
    gemm1_kernel<<<(NNODES + 63) / 64, 256, 196608>>>(x4, Wl1, Wr1, bl1);
    gemm2_kernel<<<(NNODES + 63) / 64, 256, 98304>>>(Wl2, Wr2, bl2);
    gather2_final_kernel<<<(NNODES * 32 + 255) / 256, 256>>>(out);
}

// round 8
// speedup vs baseline: 1.4766x; 1.1118x over previous
#include <cuda_runtime.h>
#include <cuda_bf16.h>

#define NNODES 50000
#define NEDGES 600000
#define CHUNK  1024
#define NCHUNK 49   // ceil(50000/1024)

// ---------------- scratch (device globals) -----------------------------------
__device__ int g_is64;
__device__ int g_cnt [NNODES];
__device__ int g_off [NNODES];
__device__ int g_cur [NNODES];
__device__ __align__(8) int g_src32[NEDGES];
__device__ __align__(8) int g_dst32[NEDGES];
__device__ int g_eidx [NEDGES];
__device__ int g_chunksum[64];
__device__ __align__(16) float g_u[NNODES * 128];   // x @ Wl1
__device__ __align__(16) float g_v[NNODES * 128];   // x @ Wr1
__device__ __align__(16) float g_h[NNODES * 128];   // layer1 output (post relu)
__device__ __align__(16) float g_p[NNODES * 64];    // h @ Wl2
__device__ __align__(16) float g_q[NNODES * 64];    // h @ Wr2 + bl2

// ---------------- f32x2 helpers -----------------------------------------------
typedef unsigned long long ull;
__device__ __forceinline__ ull pk2(float x, float y) {
    ull r; asm("mov.b64 %0, {%1, %2};" : "=l"(r) : "f"(x), "f"(y)); return r;
}
__device__ __forceinline__ ull pkdup(float x) {
    ull r; asm("mov.b64 %0, {%1, %1};" : "=l"(r) : "f"(x)); return r;
}
__device__ __forceinline__ void ffma2(ull& d, ull a, ull b) {
    asm("fma.rn.f32x2 %0, %1, %2, %0;" : "+l"(d) : "l"(a), "l"(b));
}
__device__ __forceinline__ float2 unpk(ull v) {
    float2 r; asm("mov.b64 {%0, %1}, %2;" : "=f"(r.x), "=f"(r.y) : "l"(v)); return r;
}

// ---------------- init: zero counts + dtype detect ---------------------------
__global__ void init_kernel(const int* __restrict__ ei32) {
    int i = blockIdx.x * blockDim.x + threadIdx.x;
    if (i < NNODES) g_cnt[i] = 0;
    if (i == 0) {
        int allzero = 1;
        #pragma unroll
        for (int j = 0; j < 64; j++)
            if (ei32[2 * j + 1] != 0) allzero = 0;
        g_is64 = allzero;
    }
}

// ---------------- hist: 2 edges per thread -----------------------------------
__global__ void hist_kernel(const void* __restrict__ ei) {
    int t = blockIdx.x * blockDim.x + threadIdx.x;
    int e = t * 2;
    if (e >= NEDGES) return;
    int s0, s1, d0, d1;
    if (g_is64) {
        const long long* e64 = (const long long*)ei;
        longlong2 ss = *(const longlong2*)(e64 + e);
        longlong2 dd = *(const longlong2*)(e64 + NEDGES + e);
        s0 = (int)ss.x; s1 = (int)ss.y; d0 = (int)dd.x; d1 = (int)dd.y;
    } else {
        const int* e32 = (const int*)ei;
        int2 ss = *(const int2*)(e32 + e);
        int2 dd = *(const int2*)(e32 + NEDGES + e);
        s0 = ss.x; s1 = ss.y; d0 = dd.x; d1 = dd.y;
    }
    s0 = min(max(s0, 0), NNODES - 1); s1 = min(max(s1, 0), NNODES - 1);
    d0 = min(max(d0, 0), NNODES - 1); d1 = min(max(d1, 0), NNODES - 1);
    *(int2*)(g_src32 + e) = make_int2(s0, s1);
    *(int2*)(g_dst32 + e) = make_int2(d0, d1);
    atomicAdd(&g_cnt[d0], 1);
    atomicAdd(&g_cnt[d1], 1);
}

// ---------------- scan phase 1: per-chunk sums --------------------------------
__global__ void scan_p1_kernel() {
    __shared__ int sm[CHUNK];
    int tid = threadIdx.x;
    int idx = blockIdx.x * CHUNK + tid;
    sm[tid] = (idx < NNODES) ? g_cnt[idx] : 0;
    __syncthreads();
    #pragma unroll
    for (int s = CHUNK / 2; s > 0; s >>= 1) {
        if (tid < s) sm[tid] += sm[tid + s];
        __syncthreads();
    }
    if (tid == 0) g_chunksum[blockIdx.x] = sm[0];
}

// ---------------- scan phase 2+3 merged: chunk offsets + local scan ----------
__global__ void scan_p23_kernel() {
    __shared__ int sums[64];
    __shared__ int sm[CHUNK];
    int tid = threadIdx.x;
    if (tid < 64) sums[tid] = (tid < NCHUNK) ? g_chunksum[tid] : 0;
    __syncthreads();
    if (tid == 0) {
        int run = 0;
        for (int i = 0; i < NCHUNK; i++) { int v = sums[i]; sums[i] = run; run += v; }
    }
    __syncthreads();
    int chunkoff = sums[blockIdx.x];

    int idx = blockIdx.x * CHUNK + tid;
    int v = (idx < NNODES) ? g_cnt[idx] : 0;
    sm[tid] = v;
    __syncthreads();
    #pragma unroll
    for (int d = 1; d < CHUNK; d <<= 1) {
        int t = (tid >= d) ? sm[tid - d] : 0;
        __syncthreads();
        sm[tid] += t;
        __syncthreads();
    }
    if (idx < NNODES) {
        int off = chunkoff + sm[tid] - v;   // exclusive
        g_off[idx] = off;
        g_cur[idx] = off;
    }
}

// ---------------- bucket fill: 2 edges per thread -----------------------------
__global__ void fill_kernel() {
    int t = blockIdx.x * blockDim.x + threadIdx.x;
    int e = t * 2;
    if (e >= NEDGES) return;
    int2 dd = *(const int2*)(g_dst32 + e);
    int2 ss = *(const int2*)(g_src32 + e);
    int pos0 = atomicAdd(&g_cur[dd.x], 1);
    if (pos0 >= 0 && pos0 < NEDGES) g_eidx[pos0] = ss.x;
    int pos1 = atomicAdd(&g_cur[dd.y], 1);
    if (pos1 >= 0 && pos1 < NEDGES) g_eidx[pos1] = ss.y;
}

// ---------------- GEMM X: u = x@Wl1 ; v = x@Wr1 (edge-independent) -----------
// BM=64, BN=256 (u cols 0..127, v cols 128..255), K=128.
// 256 threads; thread tile 8 rows (4 M-pairs) x 8 cols (4 u + 4 v).
// SMEM: Ws[128][256] 128KB + As[128][64] k-major 32KB = 160KB.
__global__ void __launch_bounds__(256, 1)
gemmX_kernel(const float4* __restrict__ x4,
             const float4* __restrict__ Wl1,   // [128][32] f4
             const float4* __restrict__ Wr1) { // [128][32] f4
    extern __shared__ float sm[];
    float* Ws = sm;                 // [128][256]
    float* As = sm + 128 * 256;     // [128][64]  k-major
    int tid = threadIdx.x;
    int tx = tid & 31, ty = tid >> 5;
    int m0 = blockIdx.x * 64;

    float4* Ws4 = (float4*)Ws;
    #pragma unroll
    for (int i = tid; i < 8192; i += 256) {
        int k = i >> 6, c = i & 63;
        Ws4[i] = (c < 32) ? Wl1[k * 32 + c] : Wr1[k * 32 + (c - 32)];
    }
    #pragma unroll
    for (int i = tid; i < 2048; i += 256) {
        int r = i & 63, c = i >> 6;   // c 0..31
        int m = m0 + r;
        float4 v = (m < NNODES) ? x4[m * 32 + c] : make_float4(0.f, 0.f, 0.f, 0.f);
        As[(4 * c + 0) * 64 + r] = v.x;
        As[(4 * c + 1) * 64 + r] = v.y;
        As[(4 * c + 2) * 64 + r] = v.z;
        As[(4 * c + 3) * 64 + r] = v.w;
    }
    __syncthreads();

    ull acc[4][8] = {};   // [m-pair][n: 0..3 u, 4..7 v]
    #pragma unroll 4
    for (int k = 0; k < 128; k++) {
        const float* arow = As + k * 64 + ty * 8;
        float4 a0 = *(const float4*)arow;
        float4 a1 = *(const float4*)(arow + 4);
        ull ap[4];
        ap[0] = pk2(a0.x, a0.y); ap[1] = pk2(a0.z, a0.w);
        ap[2] = pk2(a1.x, a1.y); ap[3] = pk2(a1.z, a1.w);
        float4 bu = Ws4[k * 64 + tx];
        float4 bv = Ws4[k * 64 + 32 + tx];
        ull bd[8];
        bd[0] = pkdup(bu.x); bd[1] = pkdup(bu.y); bd[2] = pkdup(bu.z); bd[3] = pkdup(bu.w);
        bd[4] = pkdup(bv.x); bd[5] = pkdup(bv.y); bd[6] = pkdup(bv.z); bd[7] = pkdup(bv.w);
        #pragma unroll
        for (int ip = 0; ip < 4; ip++) {
            #pragma unroll
            for (int j = 0; j < 8; j++) ffma2(acc[ip][j], ap[ip], bd[j]);
        }
    }

    float4* u4 = (float4*)g_u;
    float4* v4 = (float4*)g_v;
    #pragma unroll
    for (int ip = 0; ip < 4; ip++) {
        float2 c0 = unpk(acc[ip][0]), c1 = unpk(acc[ip][1]);
        float2 c2 = unpk(acc[ip][2]), c3 = unpk(acc[ip][3]);
        float2 c4 = unpk(acc[ip][4]), c5 = unpk(acc[ip][5]);
        float2 c6 = unpk(acc[ip][6]), c7 = unpk(acc[ip][7]);
        int m = m0 + ty * 8 + 2 * ip;
        if (m < NNODES) {
            u4[m * 32 + tx] = make_float4(c0.x, c1.x, c2.x, c3.x);
            v4[m * 32 + tx] = make_float4(c4.x, c5.x, c6.x, c7.x);
        }
        if (m + 1 < NNODES) {
            u4[(m + 1) * 32 + tx] = make_float4(c0.y, c1.y, c2.y, c3.y);
            v4[(m + 1) * 32 + tx] = make_float4(c4.y, c5.y, c6.y, c7.y);
        }
    }
}

// ---------------- gatherH: h = relu(mean_agg(u) + bl1 + v) --------------------
__global__ void gatherH_kernel(const float4* __restrict__ bl1) {
    int w    = (blockIdx.x * blockDim.x + threadIdx.x) >> 5;
    int lane = threadIdx.x & 31;
    if (w >= NNODES) return;
    int beg = g_off[w];
    int c   = g_cnt[w];
    const float4* u4 = (const float4*)g_u;
    float4 acc = make_float4(0.f, 0.f, 0.f, 0.f);
    int i = 0;
    for (; i + 3 < c; i += 4) {
        int s0 = g_eidx[beg + i];
        int s1 = g_eidx[beg + i + 1];
        int s2 = g_eidx[beg + i + 2];
        int s3 = g_eidx[beg + i + 3];
        float4 v0 = u4[s0 * 32 + lane];
        float4 v1 = u4[s1 * 32 + lane];
        float4 v2 = u4[s2 * 32 + lane];
        float4 v3 = u4[s3 * 32 + lane];
        acc.x += (v0.x + v1.x) + (v2.x + v3.x);
        acc.y += (v0.y + v1.y) + (v2.y + v3.y);
        acc.z += (v0.z + v1.z) + (v2.z + v3.z);
        acc.w += (v0.w + v1.w) + (v2.w + v3.w);
    }
    for (; i < c; i++) {
        int s0 = g_eidx[beg + i];
        float4 v0 = u4[s0 * 32 + lane];
        acc.x += v0.x; acc.y += v0.y; acc.z += v0.z; acc.w += v0.w;
    }
    float rd = 1.0f / (float)max(c, 1);
    float4 b  = bl1[lane];
    float4 vv = ((const float4*)g_v)[w * 32 + lane];
    float4 o;
    o.x = fmaxf(acc.x * rd + b.x + vv.x, 0.f);
    o.y = fmaxf(acc.y * rd + b.y + vv.y, 0.f);
    o.z = fmaxf(acc.z * rd + b.z + vv.z, 0.f);
    o.w = fmaxf(acc.w * rd + b.w + vv.w, 0.f);
    ((float4*)g_h)[w * 32 + lane] = o;
}

// ---------------- GEMM2: p = h@Wl2 ; q = h@Wr2 + bl2 -------------------------
// BM=64, BN=128 (cols 0..63 -> p, 64..127 -> q), K=128.
// SMEM: Ws 64KB + As 32KB = 96KB -> 2 blocks/SM.
__global__ void __launch_bounds__(256, 2)
gemm2_kernel(const float4* __restrict__ Wl2,   // [128][16] f4
             const float4* __restrict__ Wr2,   // [128][16] f4
             const float4* __restrict__ bl2) { // [16] f4
    extern __shared__ float sm[];
    float* Ws = sm;                 // [128][128]
    float* As = sm + 128 * 128;     // [128][64]  k-major
    int tid = threadIdx.x;
    int tx = tid & 31, ty = tid >> 5;
    int m0 = blockIdx.x * 64;

    float4* Ws4 = (float4*)Ws;
    #pragma unroll
    for (int i = tid; i < 4096; i += 256) {
        int k = i >> 5, c = i & 31;
        Ws4[i] = (c < 16) ? Wl2[k * 16 + c] : Wr2[k * 16 + (c - 16)];
    }
    const float4* h4 = (const float4*)g_h;
    #pragma unroll
    for (int i = tid; i < 2048; i += 256) {
        int r = i & 63, c = i >> 6;   // c 0..31
        int m = m0 + r;
        float4 v = (m < NNODES) ? h4[m * 32 + c] : make_float4(0.f, 0.f, 0.f, 0.f);
        As[(4 * c + 0) * 64 + r] = v.x;
        As[(4 * c + 1) * 64 + r] = v.y;
        As[(4 * c + 2) * 64 + r] = v.z;
        As[(4 * c + 3) * 64 + r] = v.w;
    }
    __syncthreads();

    ull acc[4][4] = {};
    #pragma unroll 4
    for (int k = 0; k < 128; k++) {
        const float* arow = As + k * 64 + ty * 8;
        float4 a0 = *(const float4*)arow;
        float4 a1 = *(const float4*)(arow + 4);
        ull ap[4];
        ap[0] = pk2(a0.x, a0.y); ap[1] = pk2(a0.z, a0.w);
        ap[2] = pk2(a1.x, a1.y); ap[3] = pk2(a1.z, a1.w);
        float4 b = Ws4[k * 32 + tx];
        ull bd0 = pkdup(b.x), bd1 = pkdup(b.y), bd2 = pkdup(b.z), bd3 = pkdup(b.w);
        #pragma unroll
        for (int ip = 0; ip < 4; ip++) {
            ffma2(acc[ip][0], ap[ip], bd0);
            ffma2(acc[ip][1], ap[ip], bd1);
            ffma2(acc[ip][2], ap[ip], bd2);
            ffma2(acc[ip][3], ap[ip], bd3);
        }
    }

    float4* p4 = (float4*)g_p;
    float4* q4 = (float4*)g_q;
    if (tx < 16) {
        #pragma unroll
        for (int ip = 0; ip < 4; ip++) {
            float2 c0 = unpk(acc[ip][0]), c1 = unpk(acc[ip][1]);
            float2 c2 = unpk(acc[ip][2]), c3 = unpk(acc[ip][3]);
            int m = m0 + ty * 8 + 2 * ip;
            if (m < NNODES)
                p4[m * 16 + tx] = make_float4(c0.x, c1.x, c2.x, c3.x);
            if (m + 1 < NNODES)
                p4[(m + 1) * 16 + tx] = make_float4(c0.y, c1.y, c2.y, c3.y);
        }
    } else {
        float4 bias = bl2[tx - 16];
        #pragma unroll
        for (int ip = 0; ip < 4; ip++) {
            float2 c0 = unpk(acc[ip][0]), c1 = unpk(acc[ip][1]);
            float2 c2 = unpk(acc[ip][2]), c3 = unpk(acc[ip][3]);
            int m = m0 + ty * 8 + 2 * ip;
            if (m < NNODES)
                q4[m * 16 + (tx - 16)] = make_float4(c0.x + bias.x, c1.x + bias.y,
                                                     c2.x + bias.z, c3.x + bias.w);
            if (m + 1 < NNODES)
                q4[(m + 1) * 16 + (tx - 16)] = make_float4(c0.y + bias.x, c1.y + bias.y,
                                                           c2.y + bias.z, c3.y + bias.w);
        }
    }
}

// ---------------- gather layer 2 + log_softmax (fused) -----------------------
__global__ void gather2_final_kernel(float* __restrict__ out) {
    int w    = (blockIdx.x * blockDim.x + threadIdx.x) >> 5;
    int lane = threadIdx.x & 31;
    if (w >= NNODES) return;
    int beg = g_off[w];
    int c   = g_cnt[w];
    const float2* p2 = (const float2*)g_p;
    float2 acc = make_float2(0.f, 0.f);
    int i = 0;
    for (; i + 3 < c; i += 4) {
        int s0 = g_eidx[beg + i];
        int s1 = g_eidx[beg + i + 1];
        int s2 = g_eidx[beg + i + 2];
        int s3 = g_eidx[beg + i + 3];
        float2 v0 = p2[s0 * 32 + lane];
        float2 v1 = p2[s1 * 32 + lane];
        float2 v2 = p2[s2 * 32 + lane];
        float2 v3 = p2[s3 * 32 + lane];
        acc.x += (v0.x + v1.x) + (v2.x + v3.x);
        acc.y += (v0.y + v1.y) + (v2.y + v3.y);
    }
    for (; i < c; i++) {
        int s0 = g_eidx[beg + i];
        float2 v0 = p2[s0 * 32 + lane];
        acc.x += v0.x; acc.y += v0.y;
    }
    float rd = 1.0f / (float)max(c, 1);
    float2 q = ((const float2*)g_q)[w * 32 + lane];
    float v0 = acc.x * rd + q.x;
    float v1 = acc.y * rd + q.y;

    float mx = fmaxf(v0, v1);
    #pragma unroll
    for (int o = 16; o; o >>= 1) mx = fmaxf(mx, __shfl_xor_sync(0xffffffffu, mx, o));
    float s = expf(v0 - mx) + expf(v1 - mx);
    #pragma unroll
    for (int o = 16; o; o >>= 1) s += __shfl_xor_sync(0xffffffffu, s, o);
    float ls = logf(s) + mx;

    ((float2*)out)[w * 32 + lane] = make_float2(v0 - ls, v1 - ls);
}

// ---------------- stream/event resources (created once, pre-checkpoint) ------
static cudaStream_t g_s2   = nullptr;
static cudaEvent_t  g_fork = nullptr;
static cudaEvent_t  g_join = nullptr;

static void ensure_resources() {
    if (!g_s2) {
        cudaStreamCreateWithFlags(&g_s2, cudaStreamNonBlocking);
        cudaEventCreateWithFlags(&g_fork, cudaEventDisableTiming);
        cudaEventCreateWithFlags(&g_join, cudaEventDisableTiming);
    }
}
namespace { struct ResInit { ResInit() { ensure_resources(); } } g_resinit; }

// ---------------- launch ------------------------------------------------------
extern "C" void kernel_launch(void* const* d_in, const int* in_sizes, int n_in,
                              void* d_out, int out_size) {
    const float4* x4   = (const float4*)d_in[0];
    const void*   ei   = d_in[1];
    const float4* Wl1  = (const float4*)d_in[2];
    const float4* bl1  = (const float4*)d_in[3];
    const float4* Wr1  = (const float4*)d_in[4];
    const float4* Wl2  = (const float4*)d_in[5];
    const float4* bl2  = (const float4*)d_in[6];
    const float4* Wr2  = (const float4*)d_in[7];
    float*        out  = (float*)d_out;

    ensure_resources();
    cudaFuncSetAttribute(gemmX_kernel, cudaFuncAttributeMaxDynamicSharedMemorySize, 163840);
    cudaFuncSetAttribute(gemm2_kernel, cudaFuncAttributeMaxDynamicSharedMemorySize, 98304);

    // ---- fork: CSR build on g_s2, concurrent with gemmX on the main stream ----
    cudaEventRecord(g_fork, 0);
    cudaStreamWaitEvent(g_s2, g_fork, 0);

    init_kernel<<<(NNODES + 255) / 256, 256, 0, g_s2>>>((const int*)ei);
    hist_kernel<<<(NEDGES / 2 + 255) / 256, 256, 0, g_s2>>>(ei);
    scan_p1_kernel<<<NCHUNK, CHUNK, 0, g_s2>>>();
    scan_p23_kernel<<<NCHUNK, CHUNK, 0, g_s2>>>();
    fill_kernel<<<(NEDGES / 2 + 255) / 256, 256, 0, g_s2>>>();
    cudaEventRecord(g_join, g_s2);

    gemmX_kernel<<<(NNODES + 63) / 64, 256, 163840>>>(x4, Wl1, Wr1);

    // ---- join ----
    cudaStreamWaitEvent(0, g_join, 0);

    gatherH_kernel<<<(NNODES * 32 + 255) / 256, 256>>>(bl1);
    gemm2_kernel<<<(NNODES + 63) / 64, 256, 98304>>>(Wl2, Wr2, bl2);
    gather2_final_kernel<<<(NNODES * 32 + 255) / 256, 256>>>(out);
}